// round 9
// baseline (speedup 1.0000x reference)
#include <cuda_runtime.h>
#include <cuda_bf16.h>
#include <cstdint>

#define NMAX 100000
#define EMAX 1600000
#define DD   64
#define NEG_SLOPE 0.01f
#define SCAN_BLK 1024
#define MAX_SBLKS 256
#define CNT_BLKS 1024

// -------- device scratch (no allocation allowed) --------
__device__ float g_dinv[NMAX];
__device__ int   g_deg[NMAX];
__device__ int   g_cursor[NMAX];
__device__ int   g_rowstart[NMAX + 2];   // LOCAL (per-1024-chunk) exclusive scan
__device__ int   g_bsums[MAX_SBLKS];     // chunk base offsets (exclusive)
__device__ int2  g_csr[EMAX];            // {src, float_as_int(coef)}
__device__ float g_h[NMAX * DD];
__device__ float g_buf[NMAX * DD];

// -------- zero --------
__global__ void k_zero(int n) {
    int i = blockIdx.x * blockDim.x + threadIdx.x;
    if (i < n) { g_deg[i] = 0; g_cursor[i] = 0; }
}

// -------- GEMM tile: h[tile] = act(in) @ W  (64x64 tile, 4x4 per thread) ----
__device__ __forceinline__ void gemm_tile(
    const float* __restrict__ in, const float* __restrict__ W,
    float* __restrict__ h, int n, int leaky_in, int tile)
{
    __shared__ float xs[64][68];
    __shared__ float ws[64][64];

    int t = threadIdx.x;
    int row0 = tile * 64;

    #pragma unroll
    for (int k = 0; k < 16; k++) {
        int idx = t + k * 256;
        ws[idx >> 6][idx & 63] = W[idx];
    }
    #pragma unroll
    for (int k = 0; k < 16; k++) {
        int idx = t + k * 256;
        int r = idx >> 6, c = idx & 63;
        int gr = row0 + r;
        float v = 0.0f;
        if (gr < n) {
            v = in[gr * DD + c];
            if (leaky_in) v = (v >= 0.0f) ? v : NEG_SLOPE * v;
        }
        xs[r][c] = v;
    }
    __syncthreads();

    int cg = (t & 15) * 4;
    int rg = (t >> 4) * 4;

    float acc[4][4];
    #pragma unroll
    for (int i = 0; i < 4; i++)
        #pragma unroll
        for (int j = 0; j < 4; j++) acc[i][j] = 0.0f;

    #pragma unroll
    for (int k = 0; k < DD; k++) {
        float4 wv = *(const float4*)&ws[k][cg];
        float x0 = xs[rg + 0][k];
        float x1 = xs[rg + 1][k];
        float x2 = xs[rg + 2][k];
        float x3 = xs[rg + 3][k];
        acc[0][0] = fmaf(x0, wv.x, acc[0][0]); acc[0][1] = fmaf(x0, wv.y, acc[0][1]);
        acc[0][2] = fmaf(x0, wv.z, acc[0][2]); acc[0][3] = fmaf(x0, wv.w, acc[0][3]);
        acc[1][0] = fmaf(x1, wv.x, acc[1][0]); acc[1][1] = fmaf(x1, wv.y, acc[1][1]);
        acc[1][2] = fmaf(x1, wv.z, acc[1][2]); acc[1][3] = fmaf(x1, wv.w, acc[1][3]);
        acc[2][0] = fmaf(x2, wv.x, acc[2][0]); acc[2][1] = fmaf(x2, wv.y, acc[2][1]);
        acc[2][2] = fmaf(x2, wv.z, acc[2][2]); acc[2][3] = fmaf(x2, wv.w, acc[2][3]);
        acc[3][0] = fmaf(x3, wv.x, acc[3][0]); acc[3][1] = fmaf(x3, wv.y, acc[3][1]);
        acc[3][2] = fmaf(x3, wv.z, acc[3][2]); acc[3][3] = fmaf(x3, wv.w, acc[3][3]);
    }

    #pragma unroll
    for (int i = 0; i < 4; i++) {
        int gr = row0 + rg + i;
        if (gr < n) {
            float4 v = make_float4(acc[i][0], acc[i][1], acc[i][2], acc[i][3]);
            *(float4*)&h[gr * DD + cg] = v;
        }
    }
}

// -------- fused: gemm1 first half + degree count --------
__global__ __launch_bounds__(256) void k_gemm1a_count(
    const float* __restrict__ x, const float* __restrict__ W1,
    float* __restrict__ h, int n, int ga,
    const int* __restrict__ dst, int e)
{
    if (blockIdx.x < ga) {
        gemm_tile(x, W1, h, n, 0, blockIdx.x);
    } else {
        int b = blockIdx.x - ga;
        for (int i = b * 256 + threadIdx.x; i < e; i += 256 * CNT_BLKS)
            atomicAdd(&g_deg[dst[i]], 1);
    }
}

// -------- fused: local scan (blocks 0..sblks-1) + dinv (rest) --------
__global__ __launch_bounds__(SCAN_BLK) void k_scan1_dinv(int n, int sblks) {
    int t = threadIdx.x;
    if ((int)blockIdx.x < sblks) {
        __shared__ int wsum[32];
        int lane = t & 31, wid = t >> 5;
        int idx = blockIdx.x * SCAN_BLK + t;
        int v = (idx < n) ? g_deg[idx] : 0;
        int x = v;
        #pragma unroll
        for (int off = 1; off < 32; off <<= 1) {
            int u = __shfl_up_sync(0xffffffffu, x, off);
            if (lane >= off) x += u;
        }
        if (lane == 31) wsum[wid] = x;
        __syncthreads();
        if (wid == 0) {
            int y = wsum[lane];
            #pragma unroll
            for (int off = 1; off < 32; off <<= 1) {
                int u = __shfl_up_sync(0xffffffffu, y, off);
                if (lane >= off) y += u;
            }
            wsum[lane] = y;
        }
        __syncthreads();
        int prefix = (wid ? wsum[wid - 1] : 0);
        if (idx <= n) g_rowstart[idx] = prefix + x - v;   // local exclusive
        if (t == SCAN_BLK - 1) g_bsums[blockIdx.x] = wsum[31];
    } else {
        int i = (blockIdx.x - sblks) * SCAN_BLK + t;
        if (i < n) g_dinv[i] = rsqrtf((float)g_deg[i] + 1.0f);
    }
}

// -------- scan chunk totals (exclusive, in place) --------
__global__ __launch_bounds__(MAX_SBLKS) void k_scan2(int nblocks) {
    __shared__ int sh[MAX_SBLKS];
    int t = threadIdx.x;
    int v = (t < nblocks) ? g_bsums[t] : 0;
    sh[t] = v;
    __syncthreads();
    for (int off = 1; off < MAX_SBLKS; off <<= 1) {
        int u = (t >= off) ? sh[t - off] : 0;
        __syncthreads();
        sh[t] += u;
        __syncthreads();
    }
    if (t < nblocks) g_bsums[t] = sh[t] - v;   // exclusive
}

// -------- fused: gemm1 second half + CSR fill --------
__global__ __launch_bounds__(256) void k_gemm1b_fill(
    const float* __restrict__ x, const float* __restrict__ W1,
    float* __restrict__ h, int n, int ga1, int gb,
    const int* __restrict__ src, const int* __restrict__ dst, int e)
{
    if ((int)blockIdx.x < gb) {
        gemm_tile(x, W1, h, n, 0, ga1 + blockIdx.x);
    } else {
        int i = (blockIdx.x - gb) * 256 + threadIdx.x;
        if (i < e) {
            int s = src[i], d = dst[i];
            int pos = atomicAdd(&g_cursor[d], 1);
            int idx = g_rowstart[d] + g_bsums[d >> 10] + pos;
            g_csr[idx] = make_int2(s, __float_as_int(g_dinv[s] * g_dinv[d]));
        }
    }
}

// -------- plain GEMM for layers 2-4 --------
__global__ __launch_bounds__(256) void k_gemm(
    const float* __restrict__ in, const float* __restrict__ W,
    float* __restrict__ h, int n)
{
    gemm_tile(in, W, h, n, 1, blockIdx.x);
}

// -------- pull: out[n] = sum coef*h[src] + dinv^2*h[n] + b --------
// 16 threads per node (one float4 each), 16 nodes per block, unroll-4 MLP
__global__ __launch_bounds__(256) void k_pull(
    const float* __restrict__ h, const float* __restrict__ b,
    float* __restrict__ out, int n, int apply_leaky)
{
    int t = threadIdx.x;
    int node = blockIdx.x * 16 + (t >> 4);
    int lane = (t & 15) << 2;
    if (node >= n) return;

    int start = g_rowstart[node]     + g_bsums[node >> 10];
    int end   = g_rowstart[node + 1] + g_bsums[(node + 1) >> 10];

    float4 acc = make_float4(0.f, 0.f, 0.f, 0.f);
    int i = start;
    for (; i + 3 < end; i += 4) {
        int2 e0 = __ldg(&g_csr[i]);
        int2 e1 = __ldg(&g_csr[i + 1]);
        int2 e2 = __ldg(&g_csr[i + 2]);
        int2 e3 = __ldg(&g_csr[i + 3]);
        float4 h0 = __ldg((const float4*)&h[e0.x * DD + lane]);
        float4 h1 = __ldg((const float4*)&h[e1.x * DD + lane]);
        float4 h2 = __ldg((const float4*)&h[e2.x * DD + lane]);
        float4 h3 = __ldg((const float4*)&h[e3.x * DD + lane]);
        float c0 = __int_as_float(e0.y), c1 = __int_as_float(e1.y);
        float c2 = __int_as_float(e2.y), c3 = __int_as_float(e3.y);
        acc.x = fmaf(c0, h0.x, acc.x); acc.y = fmaf(c0, h0.y, acc.y);
        acc.z = fmaf(c0, h0.z, acc.z); acc.w = fmaf(c0, h0.w, acc.w);
        acc.x = fmaf(c1, h1.x, acc.x); acc.y = fmaf(c1, h1.y, acc.y);
        acc.z = fmaf(c1, h1.z, acc.z); acc.w = fmaf(c1, h1.w, acc.w);
        acc.x = fmaf(c2, h2.x, acc.x); acc.y = fmaf(c2, h2.y, acc.y);
        acc.z = fmaf(c2, h2.z, acc.z); acc.w = fmaf(c2, h2.w, acc.w);
        acc.x = fmaf(c3, h3.x, acc.x); acc.y = fmaf(c3, h3.y, acc.y);
        acc.z = fmaf(c3, h3.z, acc.z); acc.w = fmaf(c3, h3.w, acc.w);
    }
    for (; i < end; i++) {
        int2 e0 = __ldg(&g_csr[i]);
        float4 h0 = __ldg((const float4*)&h[e0.x * DD + lane]);
        float c0 = __int_as_float(e0.y);
        acc.x = fmaf(c0, h0.x, acc.x); acc.y = fmaf(c0, h0.y, acc.y);
        acc.z = fmaf(c0, h0.z, acc.z); acc.w = fmaf(c0, h0.w, acc.w);
    }

    float di = g_dinv[node];
    float d2 = di * di;
    float4 hv = __ldg((const float4*)&h[node * DD + lane]);
    float4 bv = __ldg((const float4*)&b[lane]);
    float4 r;
    r.x = acc.x + d2 * hv.x + bv.x;
    r.y = acc.y + d2 * hv.y + bv.y;
    r.z = acc.z + d2 * hv.z + bv.z;
    r.w = acc.w + d2 * hv.w + bv.w;
    if (apply_leaky) {
        r.x = (r.x >= 0.f) ? r.x : NEG_SLOPE * r.x;
        r.y = (r.y >= 0.f) ? r.y : NEG_SLOPE * r.y;
        r.z = (r.z >= 0.f) ? r.z : NEG_SLOPE * r.z;
        r.w = (r.w >= 0.f) ? r.w : NEG_SLOPE * r.w;
    }
    *(float4*)&out[node * DD + lane] = r;
}

extern "C" void kernel_launch(void* const* d_in, const int* in_sizes, int n_in,
                              void* d_out, int out_size)
{
    const float* x  = (const float*)d_in[0];
    const int*   ei = (const int*)d_in[1];
    const float* W[4] = { (const float*)d_in[2], (const float*)d_in[4],
                          (const float*)d_in[6], (const float*)d_in[8] };
    const float* B[4] = { (const float*)d_in[3], (const float*)d_in[5],
                          (const float*)d_in[7], (const float*)d_in[9] };
    float* outp = (float*)d_out;

    int n = in_sizes[0] / DD;
    int e = in_sizes[1] / 2;
    const int* src = ei;
    const int* dst = ei + e;

    float* hbuf; cudaGetSymbolAddress((void**)&hbuf, g_h);
    float* buf;  cudaGetSymbolAddress((void**)&buf,  g_buf);

    int gemm_blocks = (n + 63) / 64;          // 1563
    int ga1 = gemm_blocks / 2;                // first half of gemm1
    int gb  = gemm_blocks - ga1;              // second half
    int sblks = (n + SCAN_BLK - 1) / SCAN_BLK;
    int fill_blocks = (e + 255) / 256;
    int pull_blocks = (n + 15) / 16;

    // ---- setup overlapped with layer-1 GEMM ----
    k_zero<<<(n + 255) / 256, 256>>>(n);
    k_gemm1a_count<<<ga1 + CNT_BLKS, 256>>>(x, W[0], hbuf, n, ga1, dst, e);
    k_scan1_dinv<<<sblks * 2, SCAN_BLK>>>(n, sblks);
    k_scan2<<<1, MAX_SBLKS>>>(sblks);
    k_gemm1b_fill<<<gb + fill_blocks, 256>>>(x, W[0], hbuf, n, ga1, gb, src, dst, e);

    // ---- layer 1 pull, then layers 2..4 ----
    k_pull<<<pull_blocks, 256>>>(hbuf, B[0], buf, n, 0);
    for (int l = 1; l < 4; l++) {
        float* layer_out = (l == 3) ? outp : buf;
        k_gemm<<<gemm_blocks, 256>>>(buf, W[l], hbuf, n);
        k_pull<<<pull_blocks, 256>>>(hbuf, B[l], layer_out, n, (l == 3) ? 1 : 0);
    }
}

// round 14
// speedup vs baseline: 1.1553x; 1.1553x over previous
#include <cuda_runtime.h>
#include <cuda_fp16.h>
#include <cstdint>

#define NMAX 100000
#define EMAX 1600000
#define DD   64
#define NEG_SLOPE 0.01f
#define SCAN_BLK 1024
#define MAX_SBLKS 256
#define CNT_BLKS 1024

// -------- device scratch (no allocation allowed) --------
__device__ float  g_dinv[NMAX];
__device__ int    g_deg[NMAX];
__device__ int    g_cursor[NMAX];
__device__ int    g_rowstart[NMAX + 1];
__device__ int    g_bsums[MAX_SBLKS];
__device__ int2   g_csr[EMAX];            // {src, float_as_int(coef)}
__device__ __half g_h[NMAX * DD];         // h = act(in) @ W, fp16 for gather BW
__device__ float  g_buf[NMAX * DD];       // layer output (pre-activation, fp32)

// -------- zero --------
__global__ void k_zero(int n) {
    int i = blockIdx.x * blockDim.x + threadIdx.x;
    if (i < n) { g_deg[i] = 0; g_cursor[i] = 0; }
}

// -------- GEMM tile: h[tile] = act(in) @ W  (64x64 tile, 4x4 per thread) ----
__device__ __forceinline__ void gemm_tile(
    const float* __restrict__ in, const float* __restrict__ W,
    __half* __restrict__ h, int n, int leaky_in, int tile)
{
    __shared__ float xs[64][68];
    __shared__ float ws[64][64];

    int t = threadIdx.x;
    int row0 = tile * 64;

    #pragma unroll
    for (int k = 0; k < 16; k++) {
        int idx = t + k * 256;
        ws[idx >> 6][idx & 63] = W[idx];
    }
    #pragma unroll
    for (int k = 0; k < 16; k++) {
        int idx = t + k * 256;
        int r = idx >> 6, c = idx & 63;
        int gr = row0 + r;
        float v = 0.0f;
        if (gr < n) {
            v = in[gr * DD + c];
            if (leaky_in) v = (v >= 0.0f) ? v : NEG_SLOPE * v;
        }
        xs[r][c] = v;
    }
    __syncthreads();

    int cg = (t & 15) * 4;
    int rg = (t >> 4) * 4;

    float acc[4][4];
    #pragma unroll
    for (int i = 0; i < 4; i++)
        #pragma unroll
        for (int j = 0; j < 4; j++) acc[i][j] = 0.0f;

    #pragma unroll
    for (int k = 0; k < DD; k++) {
        float4 wv = *(const float4*)&ws[k][cg];
        float x0 = xs[rg + 0][k];
        float x1 = xs[rg + 1][k];
        float x2 = xs[rg + 2][k];
        float x3 = xs[rg + 3][k];
        acc[0][0] = fmaf(x0, wv.x, acc[0][0]); acc[0][1] = fmaf(x0, wv.y, acc[0][1]);
        acc[0][2] = fmaf(x0, wv.z, acc[0][2]); acc[0][3] = fmaf(x0, wv.w, acc[0][3]);
        acc[1][0] = fmaf(x1, wv.x, acc[1][0]); acc[1][1] = fmaf(x1, wv.y, acc[1][1]);
        acc[1][2] = fmaf(x1, wv.z, acc[1][2]); acc[1][3] = fmaf(x1, wv.w, acc[1][3]);
        acc[2][0] = fmaf(x2, wv.x, acc[2][0]); acc[2][1] = fmaf(x2, wv.y, acc[2][1]);
        acc[2][2] = fmaf(x2, wv.z, acc[2][2]); acc[2][3] = fmaf(x2, wv.w, acc[2][3]);
        acc[3][0] = fmaf(x3, wv.x, acc[3][0]); acc[3][1] = fmaf(x3, wv.y, acc[3][1]);
        acc[3][2] = fmaf(x3, wv.z, acc[3][2]); acc[3][3] = fmaf(x3, wv.w, acc[3][3]);
    }

    #pragma unroll
    for (int i = 0; i < 4; i++) {
        int gr = row0 + rg + i;
        if (gr < n) {
            __half2 lo = __float22half2_rn(make_float2(acc[i][0], acc[i][1]));
            __half2 hi = __float22half2_rn(make_float2(acc[i][2], acc[i][3]));
            uint2 p;
            p.x = *reinterpret_cast<unsigned*>(&lo);
            p.y = *reinterpret_cast<unsigned*>(&hi);
            *(uint2*)&h[gr * DD + cg] = p;
        }
    }
}

// -------- fused: FULL gemm1 + degree count (count hides under gemm) --------
__global__ __launch_bounds__(256) void k_gemm1_count(
    const float* __restrict__ x, const float* __restrict__ W1,
    __half* __restrict__ h, int n, int gblocks,
    const int* __restrict__ dst, int e)
{
    if ((int)blockIdx.x < gblocks) {
        gemm_tile(x, W1, h, n, 0, blockIdx.x);
    } else {
        int b = blockIdx.x - gblocks;
        for (int i = b * 256 + threadIdx.x; i < e; i += 256 * CNT_BLKS)
            atomicAdd(&g_deg[dst[i]], 1);
    }
}

// -------- local scan (blocks 0..sblks-1) + dinv (rest) --------
__global__ __launch_bounds__(SCAN_BLK) void k_scan1_dinv(int n, int sblks) {
    int t = threadIdx.x;
    if ((int)blockIdx.x < sblks) {
        __shared__ int wsum[32];
        int lane = t & 31, wid = t >> 5;
        int idx = blockIdx.x * SCAN_BLK + t;
        int v = (idx < n) ? g_deg[idx] : 0;
        int x = v;
        #pragma unroll
        for (int off = 1; off < 32; off <<= 1) {
            int u = __shfl_up_sync(0xffffffffu, x, off);
            if (lane >= off) x += u;
        }
        if (lane == 31) wsum[wid] = x;
        __syncthreads();
        if (wid == 0) {
            int y = wsum[lane];
            #pragma unroll
            for (int off = 1; off < 32; off <<= 1) {
                int u = __shfl_up_sync(0xffffffffu, y, off);
                if (lane >= off) y += u;
            }
            wsum[lane] = y;
        }
        __syncthreads();
        int prefix = (wid ? wsum[wid - 1] : 0);
        if (idx < n) g_rowstart[idx] = prefix + x - v;   // local exclusive
        if (t == SCAN_BLK - 1) g_bsums[blockIdx.x] = wsum[31];
    } else {
        int i = (blockIdx.x - sblks) * SCAN_BLK + t;
        if (i < n) g_dinv[i] = rsqrtf((float)g_deg[i] + 1.0f);
    }
}

// -------- scan chunk totals --------
__global__ __launch_bounds__(MAX_SBLKS) void k_scan2(int nblocks, int n) {
    __shared__ int sh[MAX_SBLKS];
    int t = threadIdx.x;
    int v = (t < nblocks) ? g_bsums[t] : 0;
    sh[t] = v;
    __syncthreads();
    for (int off = 1; off < MAX_SBLKS; off <<= 1) {
        int u = (t >= off) ? sh[t - off] : 0;
        __syncthreads();
        sh[t] += u;
        __syncthreads();
    }
    if (t < nblocks) g_bsums[t] = sh[t] - v;   // exclusive
    if (t == MAX_SBLKS - 1) g_rowstart[n] = sh[MAX_SBLKS - 1];
}

// -------- add chunk offsets --------
__global__ __launch_bounds__(SCAN_BLK) void k_scan3(int n) {
    int idx = blockIdx.x * SCAN_BLK + threadIdx.x;
    if (idx < n) g_rowstart[idx] += g_bsums[blockIdx.x];
}

// -------- CSR fill --------
__global__ void k_fill(const int* __restrict__ src, const int* __restrict__ dst, int e) {
    int i = blockIdx.x * blockDim.x + threadIdx.x;
    if (i >= e) return;
    int s = src[i], d = dst[i];
    int pos = atomicAdd(&g_cursor[d], 1);
    int idx = g_rowstart[d] + pos;
    g_csr[idx] = make_int2(s, __float_as_int(g_dinv[s] * g_dinv[d]));
}

// -------- plain GEMM for layers 2-4 --------
__global__ __launch_bounds__(256) void k_gemm(
    const float* __restrict__ in, const float* __restrict__ W,
    __half* __restrict__ h, int n)
{
    gemm_tile(in, W, h, n, 1, blockIdx.x);
}

// -------- pull: out[n] = sum coef*h16[src] + dinv^2*h16[n] + b --------
// 16 threads/node, each thread handles 4 features (uint2 = 4 halves per edge)
__device__ __forceinline__ float4 h4f(uint2 p) {
    __half2 lo = *reinterpret_cast<__half2*>(&p.x);
    __half2 hi = *reinterpret_cast<__half2*>(&p.y);
    float2 f0 = __half22float2(lo);
    float2 f1 = __half22float2(hi);
    return make_float4(f0.x, f0.y, f1.x, f1.y);
}

__global__ __launch_bounds__(256) void k_pull(
    const __half* __restrict__ h, const float* __restrict__ b,
    float* __restrict__ out, int n, int apply_leaky)
{
    int t = threadIdx.x;
    int node = blockIdx.x * 16 + (t >> 4);
    int lane = (t & 15) << 2;   // feature offset, 4 features per thread
    if (node >= n) return;

    int start = g_rowstart[node];
    int end   = g_rowstart[node + 1];

    float4 acc = make_float4(0.f, 0.f, 0.f, 0.f);
    int i = start;
    for (; i + 3 < end; i += 4) {
        int2 e0 = __ldg(&g_csr[i]);
        int2 e1 = __ldg(&g_csr[i + 1]);
        int2 e2 = __ldg(&g_csr[i + 2]);
        int2 e3 = __ldg(&g_csr[i + 3]);
        float4 h0 = h4f(__ldg((const uint2*)&h[e0.x * DD + lane]));
        float4 h1 = h4f(__ldg((const uint2*)&h[e1.x * DD + lane]));
        float4 h2 = h4f(__ldg((const uint2*)&h[e2.x * DD + lane]));
        float4 h3 = h4f(__ldg((const uint2*)&h[e3.x * DD + lane]));
        float c0 = __int_as_float(e0.y), c1 = __int_as_float(e1.y);
        float c2 = __int_as_float(e2.y), c3 = __int_as_float(e3.y);
        acc.x = fmaf(c0, h0.x, acc.x); acc.y = fmaf(c0, h0.y, acc.y);
        acc.z = fmaf(c0, h0.z, acc.z); acc.w = fmaf(c0, h0.w, acc.w);
        acc.x = fmaf(c1, h1.x, acc.x); acc.y = fmaf(c1, h1.y, acc.y);
        acc.z = fmaf(c1, h1.z, acc.z); acc.w = fmaf(c1, h1.w, acc.w);
        acc.x = fmaf(c2, h2.x, acc.x); acc.y = fmaf(c2, h2.y, acc.y);
        acc.z = fmaf(c2, h2.z, acc.z); acc.w = fmaf(c2, h2.w, acc.w);
        acc.x = fmaf(c3, h3.x, acc.x); acc.y = fmaf(c3, h3.y, acc.y);
        acc.z = fmaf(c3, h3.z, acc.z); acc.w = fmaf(c3, h3.w, acc.w);
    }
    for (; i < end; i++) {
        int2 e0 = __ldg(&g_csr[i]);
        float4 h0 = h4f(__ldg((const uint2*)&h[e0.x * DD + lane]));
        float c0 = __int_as_float(e0.y);
        acc.x = fmaf(c0, h0.x, acc.x); acc.y = fmaf(c0, h0.y, acc.y);
        acc.z = fmaf(c0, h0.z, acc.z); acc.w = fmaf(c0, h0.w, acc.w);
    }

    float di = g_dinv[node];
    float d2 = di * di;
    float4 hv = h4f(__ldg((const uint2*)&h[node * DD + lane]));
    float4 bv = __ldg((const float4*)&b[lane]);
    float4 r;
    r.x = acc.x + d2 * hv.x + bv.x;
    r.y = acc.y + d2 * hv.y + bv.y;
    r.z = acc.z + d2 * hv.z + bv.z;
    r.w = acc.w + d2 * hv.w + bv.w;
    if (apply_leaky) {
        r.x = (r.x >= 0.f) ? r.x : NEG_SLOPE * r.x;
        r.y = (r.y >= 0.f) ? r.y : NEG_SLOPE * r.y;
        r.z = (r.z >= 0.f) ? r.z : NEG_SLOPE * r.z;
        r.w = (r.w >= 0.f) ? r.w : NEG_SLOPE * r.w;
    }
    *(float4*)&out[node * DD + lane] = r;
}

extern "C" void kernel_launch(void* const* d_in, const int* in_sizes, int n_in,
                              void* d_out, int out_size)
{
    const float* x  = (const float*)d_in[0];
    const int*   ei = (const int*)d_in[1];
    const float* W[4] = { (const float*)d_in[2], (const float*)d_in[4],
                          (const float*)d_in[6], (const float*)d_in[8] };
    const float* B[4] = { (const float*)d_in[3], (const float*)d_in[5],
                          (const float*)d_in[7], (const float*)d_in[9] };
    float* outp = (float*)d_out;

    int n = in_sizes[0] / DD;
    int e = in_sizes[1] / 2;
    const int* src = ei;
    const int* dst = ei + e;

    __half* hbuf; cudaGetSymbolAddress((void**)&hbuf, g_h);
    float*  buf;  cudaGetSymbolAddress((void**)&buf,  g_buf);

    int gemm_blocks = (n + 63) / 64;
    int sblks = (n + SCAN_BLK - 1) / SCAN_BLK;
    int pull_blocks = (n + 15) / 16;

    // ---- setup; degree count hidden under full layer-1 GEMM ----
    k_zero<<<(n + 255) / 256, 256>>>(n);
    k_gemm1_count<<<gemm_blocks + CNT_BLKS, 256>>>(x, W[0], hbuf, n, gemm_blocks, dst, e);
    k_scan1_dinv<<<sblks * 2, SCAN_BLK>>>(n, sblks);
    k_scan2<<<1, MAX_SBLKS>>>(sblks, n);
    k_scan3<<<sblks, SCAN_BLK>>>(n);
    k_fill<<<(e + 255) / 256, 256>>>(src, dst, e);

    // ---- layer 1 pull, then layers 2..4 ----
    k_pull<<<pull_blocks, 256>>>(hbuf, B[0], buf, n, 0);
    for (int l = 1; l < 4; l++) {
        float* layer_out = (l == 3) ? outp : buf;
        k_gemm<<<gemm_blocks, 256>>>(buf, W[l], hbuf, n);
        k_pull<<<pull_blocks, 256>>>(hbuf, B[l], layer_out, n, (l == 3) ? 1 : 0);
    }
}